// round 1
// baseline (speedup 1.0000x reference)
#include <cuda_runtime.h>
#include <math.h>

#define BS   4
#define V    4096
#define NNB  32
#define CIN  128
#define COUT 256
#define NROWS (BS*V)        // 16384 distinct (b, j) rows
#define NPOS  (BS*V*NNB)    // 524288 gather positions

// ---- scratch (no allocation allowed; device globals) ----
__device__ int   g_cnt[NROWS];
__device__ float g_zt[NROWS * COUT];          // 16 MB: z-tilde (pre-BN linear output)
__device__ float g_part[256 * 2 * 2 * 128];   // [rowblk][colblk][sum|sumsq][128]
__device__ float g_scale[COUT];
__device__ float g_shift[COUT];

// ---------------------------------------------------------------------------
__global__ void k_zero_cnt() {
    int i = blockIdx.x * blockDim.x + threadIdx.x;
    if (i < NROWS) g_cnt[i] = 0;
}

__global__ void k_hist(const int* __restrict__ nbr) {
    int i = blockIdx.x * blockDim.x + threadIdx.x;
    if (i < NPOS) {
        int b = i >> 17;                    // / (V*NNB) = 131072
        atomicAdd(&g_cnt[(b << 12) + nbr[i]], 1);
    }
}

// ---------------------------------------------------------------------------
// z~ = [features | fdist] @ W^T + bias   (16384 x 128) @ (128 x 256)
// Block tile: 64 rows x 128 cols, full K=128 in smem. 256 threads,
// each thread: 8 rows x 4 cols. Also emits weighted per-channel
// partial sum / sumsq (weight = neighbor count) for BN stats.
__global__ void __launch_bounds__(256) k_gemm(const float* __restrict__ fm,
                                              const float* __restrict__ W,
                                              const float* __restrict__ bias) {
    extern __shared__ float sm[];
    float* As   = sm;                 // 64*128 floats
    float* Ws   = sm + 64 * 128;      // 128*128 floats (float4-swizzled)
    float* cntf = Ws + 128 * 128;     // 64 floats
    float* red  = As;                 // reused after main loop (2*8*128 floats)

    const int tid  = threadIdx.x;
    const int rb   = blockIdx.y;
    const int cb   = blockIdx.x;
    const int row0 = rb * 64;

    if (tid < 64) cntf[tid] = (float)g_cnt[row0 + tid];

    // Load A tile: 64 rows x (127 features + fdist slot initialized to 0)
    #pragma unroll
    for (int i = 0; i < 32; i++) {
        int e = i * 256 + tid;
        int r = e >> 7, k = e & 127;
        As[r * 128 + k] = (k < 127) ? fm[(row0 + r) * 127 + k] : 0.f;
    }

    // Load W tile transposed into smem with float4-granular XOR swizzle.
    // Element (k, c) lives at Ws[k*128 + ((c>>2)^(k&31))*4 + (c&3)].
    #pragma unroll
    for (int i = 0; i < 16; i++) {
        int e  = i * 256 + tid;
        int c  = e >> 5;       // local col 0..127
        int k4 = e & 31;
        float4 wv = *reinterpret_cast<const float4*>(&W[(cb * 128 + c) * 128 + k4 * 4]);
        int cq = c >> 2, cl = c & 3;
        float wa[4] = {wv.x, wv.y, wv.z, wv.w};
        #pragma unroll
        for (int j = 0; j < 4; j++) {
            int k = k4 * 4 + j;
            Ws[k * 128 + ((cq ^ (k & 31)) << 2) + cl] = wa[j];
        }
    }
    __syncthreads();

    // fdist per row: warp w reduces rows 8w..8w+7 (deterministic shfl tree)
    {
        int w = tid >> 5, ln = tid & 31;
        #pragma unroll
        for (int rr = 0; rr < 8; rr++) {
            int r = w * 8 + rr;
            float s = 0.f;
            #pragma unroll
            for (int q = 0; q < 4; q++) {
                int k = q * 32 + ln;
                float a = (k < 127) ? As[r * 128 + k] : 0.f;
                s += a * a;
            }
            #pragma unroll
            for (int off = 16; off; off >>= 1)
                s += __shfl_xor_sync(0xffffffffu, s, off);
            if (ln == 0) As[r * 128 + 127] = sqrtf(s);
        }
    }
    __syncthreads();

    const int tc = tid & 31;   // col group (4 cols)
    const int tr = tid >> 5;   // row group (8 rows); constant per warp -> A reads broadcast
    float acc[8][4];
    #pragma unroll
    for (int m = 0; m < 8; m++)
        #pragma unroll
        for (int j = 0; j < 4; j++) acc[m][j] = 0.f;

    #pragma unroll 4
    for (int k = 0; k < 128; k++) {
        float4 w4 = *reinterpret_cast<const float4*>(&Ws[k * 128 + ((tc ^ (k & 31)) << 2)]);
        float a[8];
        #pragma unroll
        for (int m = 0; m < 8; m++) a[m] = As[(tr * 8 + m) * 128 + k];
        #pragma unroll
        for (int m = 0; m < 8; m++) {
            acc[m][0] = fmaf(a[m], w4.x, acc[m][0]);
            acc[m][1] = fmaf(a[m], w4.y, acc[m][1]);
            acc[m][2] = fmaf(a[m], w4.z, acc[m][2]);
            acc[m][3] = fmaf(a[m], w4.w, acc[m][3]);
        }
    }

    // Epilogue: +bias, store z~, weighted moment partials
    float4 bv = *reinterpret_cast<const float4*>(&bias[cb * 128 + tc * 4]);
    float ps[4] = {0.f, 0.f, 0.f, 0.f};
    float pq[4] = {0.f, 0.f, 0.f, 0.f};
    #pragma unroll
    for (int m = 0; m < 8; m++) {
        int gr   = row0 + tr * 8 + m;
        float cw = cntf[tr * 8 + m];
        float4 z;
        z.x = acc[m][0] + bv.x;
        z.y = acc[m][1] + bv.y;
        z.z = acc[m][2] + bv.z;
        z.w = acc[m][3] + bv.w;
        *reinterpret_cast<float4*>(&g_zt[gr * COUT + cb * 128 + tc * 4]) = z;
        ps[0] += cw * z.x;  pq[0] += cw * z.x * z.x;
        ps[1] += cw * z.y;  pq[1] += cw * z.y * z.y;
        ps[2] += cw * z.z;  pq[2] += cw * z.z * z.z;
        ps[3] += cw * z.w;  pq[3] += cw * z.w * z.w;
    }
    __syncthreads();  // everyone done reading As -> safe to reuse as 'red'
    #pragma unroll
    for (int j = 0; j < 4; j++) {
        red[tr * 128 + tc * 4 + j]        = ps[j];
        red[1024 + tr * 128 + tc * 4 + j] = pq[j];
    }
    __syncthreads();
    {
        int q = tid >> 7, c = tid & 127;
        float s = 0.f;
        #pragma unroll
        for (int t = 0; t < 8; t++) s += red[q * 1024 + t * 128 + c];
        g_part[((rb * 2 + cb) * 2 + q) * 128 + c] = s;
    }
}

// ---------------------------------------------------------------------------
// Fold BN(mean,var) + gamma/beta into per-channel scale/shift. Deterministic
// fixed-order reduction over 256 row-block partials.
__global__ void k_stats(const float* __restrict__ gamma,
                        const float* __restrict__ beta) {
    int c = threadIdx.x;               // 256 channels
    int cbk = c >> 7, cc = c & 127;
    float S = 0.f, Q = 0.f;
    for (int rb = 0; rb < 256; rb++) {
        S += g_part[((rb * 2 + cbk) * 2 + 0) * 128 + cc];
        Q += g_part[((rb * 2 + cbk) * 2 + 1) * 128 + cc];
    }
    const float invN = 1.f / (float)NPOS;
    float mean = S * invN;
    float var  = Q * invN - mean * mean;     // biased variance
    float sc   = gamma[c] * rsqrtf(var + 1e-5f);
    g_scale[c] = sc;
    g_shift[c] = beta[c] - mean * sc;
}

// ---------------------------------------------------------------------------
// Final pass: per (b,v) block. Warp 0 builds direction weights for 32
// neighbors; then thread c gathers z~[b, j_n, c] for n=0..31 (L2 resident),
// applies BN-affine + relu, theta = relu(dirw . sup_w + d0), max-pool.
__global__ void __launch_bounds__(256) k_pool(const int* __restrict__ nbr,
                                              const float* __restrict__ verts,
                                              const float* __restrict__ dirs,
                                              float* __restrict__ out) {
    __shared__ float dw0[32], dw1[32], dw2[32];
    __shared__ int offs[32];
    const int bx  = blockIdx.x;        // (b,v) linear
    const int b   = bx >> 12;
    const int tid = threadIdx.x;

    if (tid < 32) {
        int j = nbr[bx * 32 + tid];
        float vx = verts[bx * 3 + 0];
        float vy = verts[bx * 3 + 1];
        float vz = verts[bx * 3 + 2];
        const float* pn = verts + ((b << 12) + j) * 3;
        float dx = pn[0] - vx, dy = pn[1] - vy, dz = pn[2] - vz;
        float nrm = fmaxf(sqrtf(dx * dx + dy * dy + dz * dz), 1e-12f);
        float inv = 1.f / nrm;
        dw0[tid] = fmaf(dx * inv, 0.5f, 0.5f);
        dw1[tid] = fmaf(dy * inv, 0.5f, 0.5f);
        dw2[tid] = fmaf(dz * inv, 0.5f, 0.5f);
        offs[tid] = ((b << 12) + j) << 8;   // row offset into g_zt
    }
    __syncthreads();

    const int c = tid;
    float d0 = dirs[c];
    float s0 = dirs[256 + c] - d0;
    float s1 = dirs[512 + c] - d0;
    float s2 = dirs[768 + c] - d0;
    float sc = g_scale[c], sh = g_shift[c];

    float acc = 0.f;   // all candidates are >= 0 (relu * relu)
    #pragma unroll
    for (int n0 = 0; n0 < 32; n0 += 8) {
        float z[8];
        #pragma unroll
        for (int u = 0; u < 8; u++) z[u] = g_zt[offs[n0 + u] + c];   // batched -> MLP 8
        #pragma unroll
        for (int u = 0; u < 8; u++) {
            int n = n0 + u;
            float th = fmaxf(fmaf(dw0[n], s0, fmaf(dw1[n], s1, fmaf(dw2[n], s2, d0))), 0.f);
            float r  = fmaxf(fmaf(z[u], sc, sh), 0.f);
            acc = fmaxf(acc, r * th);
        }
    }
    out[(bx << 8) + c] = acc;
}

// ---------------------------------------------------------------------------
extern "C" void kernel_launch(void* const* d_in, const int* in_sizes, int n_in,
                              void* d_out, int out_size) {
    const int*   nbr   = (const int*)d_in[0];
    const float* verts = (const float*)d_in[1];
    const float* fm    = (const float*)d_in[2];
    const float* dirs  = (const float*)d_in[3];
    const float* W     = (const float*)d_in[4];
    const float* bias  = (const float*)d_in[5];
    const float* gamma = (const float*)d_in[6];
    const float* beta  = (const float*)d_in[7];
    float* out = (float*)d_out;

    const int smem_gemm = (64 * 128 + 128 * 128 + 64) * (int)sizeof(float); // 98,560 B
    cudaFuncSetAttribute(k_gemm, cudaFuncAttributeMaxDynamicSharedMemorySize, smem_gemm);

    k_zero_cnt<<<(NROWS + 255) / 256, 256>>>();
    k_hist<<<NPOS / 512, 512>>>(nbr);
    k_gemm<<<dim3(2, 256), 256, smem_gemm>>>(fm, W, bias);
    k_stats<<<1, 256>>>(gamma, beta);
    k_pool<<<NROWS, 256>>>(nbr, verts, dirs, out);
}

// round 2
// speedup vs baseline: 1.0470x; 1.0470x over previous
#include <cuda_runtime.h>
#include <cuda_fp16.h>
#include <math.h>

#define BS   4
#define V    4096
#define NNB  32
#define CIN  128
#define COUT 256
#define NROWS (BS*V)        // 16384 distinct (b, j) rows
#define NPOS  (BS*V*NNB)    // 524288 gather positions

// ---- scratch (no allocation allowed; device globals) ----
__device__ int    g_cnt[NROWS];
__device__ __half g_zt[NROWS * COUT];         // 8 MB: z-tilde (pre-BN), fp16
__device__ float  g_part[256 * 512];          // rb-major: rb*512 + cbk*256 + q*128 + cc
__device__ float  g_part2[32 * 512];
__device__ float  g_scale[COUT];
__device__ float  g_shift[COUT];

// ---------------------------------------------------------------------------
__global__ void k_zero_cnt() {
    int i = blockIdx.x * blockDim.x + threadIdx.x;
    if (i < NROWS) g_cnt[i] = 0;
}

__global__ void k_hist(const int* __restrict__ nbr) {
    int i = blockIdx.x * blockDim.x + threadIdx.x;
    if (i < NPOS) {
        int b = i >> 17;                    // / (V*NNB) = 131072
        atomicAdd(&g_cnt[(b << 12) + nbr[i]], 1);
    }
}

// ---------------------------------------------------------------------------
// z~ = [features | fdist] @ W^T + bias   (16384 x 128) @ (128 x 256)
// Block tile 64x128, K=128 resident. 256 threads, each 8 rows x 4 cols.
// Mainloop uses packed fma.rn.f32x2 (FFMA2) for 2x fp32 throughput.
// Emits weighted per-channel sum/sumsq partials (weight = neighbor count).
__global__ void __launch_bounds__(256) k_gemm(const float* __restrict__ fm,
                                              const float* __restrict__ W,
                                              const float* __restrict__ bias) {
    extern __shared__ float sm[];
    float* As   = sm;                 // 64*128
    float* Ws   = sm + 64 * 128;      // 128*128 (float4-swizzled)
    float* cntf = Ws + 128 * 128;     // 64
    float* red  = As;                 // reused post-mainloop

    const int tid  = threadIdx.x;
    const int rb   = blockIdx.y;
    const int cb   = blockIdx.x;
    const int row0 = rb * 64;

    if (tid < 64) cntf[tid] = (float)g_cnt[row0 + tid];

    // A tile: 64 rows x (127 features + fdist slot)
    #pragma unroll
    for (int i = 0; i < 32; i++) {
        int e = i * 256 + tid;
        int r = e >> 7, k = e & 127;
        As[r * 128 + k] = (k < 127) ? fm[(row0 + r) * 127 + k] : 0.f;
    }

    // W tile transposed, float4-granular XOR swizzle:
    // element (k, c) -> Ws[k*128 + ((c>>2)^(k&31))*4 + (c&3)]
    #pragma unroll
    for (int i = 0; i < 16; i++) {
        int e  = i * 256 + tid;
        int c  = e >> 5;
        int k4 = e & 31;
        float4 wv = *reinterpret_cast<const float4*>(&W[(cb * 128 + c) * 128 + k4 * 4]);
        int cq = c >> 2, cl = c & 3;
        float wa[4] = {wv.x, wv.y, wv.z, wv.w};
        #pragma unroll
        for (int j = 0; j < 4; j++) {
            int k = k4 * 4 + j;
            Ws[k * 128 + ((cq ^ (k & 31)) << 2) + cl] = wa[j];
        }
    }
    __syncthreads();

    // fdist per row: warp w handles rows 8w..8w+7 (deterministic shfl tree)
    {
        int w = tid >> 5, ln = tid & 31;
        #pragma unroll
        for (int rr = 0; rr < 8; rr++) {
            int r = w * 8 + rr;
            float s = 0.f;
            #pragma unroll
            for (int q = 0; q < 4; q++) {
                int k = q * 32 + ln;
                float a = (k < 127) ? As[r * 128 + k] : 0.f;
                s += a * a;
            }
            #pragma unroll
            for (int off = 16; off; off >>= 1)
                s += __shfl_xor_sync(0xffffffffu, s, off);
            if (ln == 0) As[r * 128 + 127] = sqrtf(s);
        }
    }
    __syncthreads();

    const int tc = tid & 31;   // col group (4 cols)
    const int tr = tid >> 5;   // row group (8 rows); warp-uniform -> A broadcast
    unsigned long long acc2[8][2];
    #pragma unroll
    for (int m = 0; m < 8; m++) { acc2[m][0] = 0ull; acc2[m][1] = 0ull; }

    #pragma unroll 2
    for (int k0 = 0; k0 < 128; k0 += 4) {
        float4 av[8];
        #pragma unroll
        for (int m = 0; m < 8; m++)
            av[m] = *reinterpret_cast<const float4*>(&As[(tr * 8 + m) * 128 + k0]);
        #pragma unroll
        for (int j = 0; j < 4; j++) {
            int k = k0 + j;
            ulonglong2 w2 = *reinterpret_cast<const ulonglong2*>(
                &Ws[k * 128 + ((tc ^ (k & 31)) << 2)]);
            #pragma unroll
            for (int m = 0; m < 8; m++) {
                float a = (j == 0) ? av[m].x : (j == 1) ? av[m].y
                        : (j == 2) ? av[m].z : av[m].w;
                unsigned long long aa;
                asm("mov.b64 %0, {%1, %1};" : "=l"(aa) : "f"(a));
                asm("fma.rn.f32x2 %0, %1, %2, %0;" : "+l"(acc2[m][0]) : "l"(aa), "l"(w2.x));
                asm("fma.rn.f32x2 %0, %1, %2, %0;" : "+l"(acc2[m][1]) : "l"(aa), "l"(w2.y));
            }
        }
    }

    // Epilogue: +bias, fp16 store, weighted moment partials (fp32, exact stats)
    float4 bv = *reinterpret_cast<const float4*>(&bias[cb * 128 + tc * 4]);
    float ps[4] = {0.f, 0.f, 0.f, 0.f};
    float pq[4] = {0.f, 0.f, 0.f, 0.f};
    #pragma unroll
    for (int m = 0; m < 8; m++) {
        int gr   = row0 + tr * 8 + m;
        float cw = cntf[tr * 8 + m];
        float z0, z1, z2, z3;
        asm("mov.b64 {%0, %1}, %2;" : "=f"(z0), "=f"(z1) : "l"(acc2[m][0]));
        asm("mov.b64 {%0, %1}, %2;" : "=f"(z2), "=f"(z3) : "l"(acc2[m][1]));
        z0 += bv.x; z1 += bv.y; z2 += bv.z; z3 += bv.w;
        __half2 h01 = __floats2half2_rn(z0, z1);
        __half2 h23 = __floats2half2_rn(z2, z3);
        union { struct { __half2 a, b; } h; uint2 u; } pk;
        pk.h.a = h01; pk.h.b = h23;
        *reinterpret_cast<uint2*>(&g_zt[gr * COUT + cb * 128 + tc * 4]) = pk.u;
        ps[0] += cw * z0;  pq[0] += cw * z0 * z0;
        ps[1] += cw * z1;  pq[1] += cw * z1 * z1;
        ps[2] += cw * z2;  pq[2] += cw * z2 * z2;
        ps[3] += cw * z3;  pq[3] += cw * z3 * z3;
    }
    __syncthreads();  // As reads done -> reuse as 'red'
    #pragma unroll
    for (int j = 0; j < 4; j++) {
        red[tr * 128 + tc * 4 + j]        = ps[j];
        red[1024 + tr * 128 + tc * 4 + j] = pq[j];
    }
    __syncthreads();
    {
        int q = tid >> 7, c = tid & 127;
        float s = 0.f;
        #pragma unroll
        for (int t = 0; t < 8; t++) s += red[q * 1024 + t * 128 + c];
        // layout: rb*512 + cbk*256 + q*128 + cc
        g_part[rb * 512 + cb * 256 + q * 128 + c] = s;
    }
}

// ---------------------------------------------------------------------------
// Stage 1: 32 blocks x 512 threads, each block folds 8 row-blocks.
__global__ void k_stats1() {
    int s   = threadIdx.x;           // 0..511
    int rb0 = blockIdx.x * 8;
    float t = 0.f;
    #pragma unroll
    for (int i = 0; i < 8; i++) t += g_part[(rb0 + i) * 512 + s];
    g_part2[blockIdx.x * 512 + s] = t;
}

// Stage 2: fold 32 partials, emit per-channel BN scale/shift.
__global__ void k_stats2(const float* __restrict__ gamma,
                         const float* __restrict__ beta) {
    int c = threadIdx.x;             // 256 channels
    int cbk = c >> 7, cc = c & 127;
    float S = 0.f, Q = 0.f;
    #pragma unroll
    for (int t = 0; t < 32; t++) {
        S += g_part2[t * 512 + cbk * 256 + cc];
        Q += g_part2[t * 512 + cbk * 256 + 128 + cc];
    }
    const float invN = 1.f / (float)NPOS;
    float mean = S * invN;
    float var  = Q * invN - mean * mean;     // biased variance
    float sc   = gamma[c] * rsqrtf(var + 1e-5f);
    g_scale[c] = sc;
    g_shift[c] = beta[c] - mean * sc;
}

// ---------------------------------------------------------------------------
// Final pass: block per (b,v). Warp 0 builds 32 direction weights; thread c
// gathers fp16 z~ rows (L2 resident), affine+relu, theta on the fly, max.
__global__ void __launch_bounds__(256) k_pool(const int* __restrict__ nbr,
                                              const float* __restrict__ verts,
                                              const float* __restrict__ dirs,
                                              float* __restrict__ out) {
    __shared__ float dw0[32], dw1[32], dw2[32];
    __shared__ int offs[32];
    const int bx  = blockIdx.x;        // (b,v) linear
    const int b   = bx >> 12;
    const int tid = threadIdx.x;

    if (tid < 32) {
        int j = nbr[bx * 32 + tid];
        float vx = verts[bx * 3 + 0];
        float vy = verts[bx * 3 + 1];
        float vz = verts[bx * 3 + 2];
        const float* pn = verts + ((b << 12) + j) * 3;
        float dx = pn[0] - vx, dy = pn[1] - vy, dz = pn[2] - vz;
        float nrm = fmaxf(sqrtf(dx * dx + dy * dy + dz * dz), 1e-12f);
        float inv = 1.f / nrm;
        dw0[tid] = fmaf(dx * inv, 0.5f, 0.5f);
        dw1[tid] = fmaf(dy * inv, 0.5f, 0.5f);
        dw2[tid] = fmaf(dz * inv, 0.5f, 0.5f);
        offs[tid] = ((b << 12) + j) << 8;   // element offset into g_zt
    }
    __syncthreads();

    const int c = tid;
    float d0 = dirs[c];
    float s0 = dirs[256 + c] - d0;
    float s1 = dirs[512 + c] - d0;
    float s2 = dirs[768 + c] - d0;
    float sc = g_scale[c], sh = g_shift[c];

    float acc = 0.f;   // candidates >= 0 (relu * relu)
    #pragma unroll
    for (int n0 = 0; n0 < 32; n0 += 8) {
        float z[8];
        #pragma unroll
        for (int u = 0; u < 8; u++)
            z[u] = __half2float(g_zt[offs[n0 + u] + c]);   // batched -> MLP 8
        #pragma unroll
        for (int u = 0; u < 8; u++) {
            int n = n0 + u;
            float th = fmaxf(fmaf(dw0[n], s0, fmaf(dw1[n], s1, fmaf(dw2[n], s2, d0))), 0.f);
            float r  = fmaxf(fmaf(z[u], sc, sh), 0.f);
            acc = fmaxf(acc, r * th);
        }
    }
    out[(bx << 8) + c] = acc;
}

// ---------------------------------------------------------------------------
extern "C" void kernel_launch(void* const* d_in, const int* in_sizes, int n_in,
                              void* d_out, int out_size) {
    const int*   nbr   = (const int*)d_in[0];
    const float* verts = (const float*)d_in[1];
    const float* fm    = (const float*)d_in[2];
    const float* dirs  = (const float*)d_in[3];
    const float* W     = (const float*)d_in[4];
    const float* bias  = (const float*)d_in[5];
    const float* gamma = (const float*)d_in[6];
    const float* beta  = (const float*)d_in[7];
    float* out = (float*)d_out;

    const int smem_gemm = (64 * 128 + 128 * 128 + 64) * (int)sizeof(float); // 98,560 B
    cudaFuncSetAttribute(k_gemm, cudaFuncAttributeMaxDynamicSharedMemorySize, smem_gemm);

    k_zero_cnt<<<(NROWS + 255) / 256, 256>>>();
    k_hist<<<NPOS / 512, 512>>>(nbr);
    k_gemm<<<dim3(2, 256), 256, smem_gemm>>>(fm, W, bias);
    k_stats1<<<32, 512>>>();
    k_stats2<<<1, 256>>>(gamma, beta);
    k_pool<<<NROWS, 256>>>(nbr, verts, dirs, out);
}

// round 3
// speedup vs baseline: 1.2211x; 1.1663x over previous
#include <cuda_runtime.h>
#include <cuda_fp16.h>
#include <math.h>

#define BS   4
#define V    4096
#define NNB  32
#define CIN  128
#define COUT 256
#define NROWS (BS*V)        // 16384 distinct (b, j) rows
#define NPOS  (BS*V*NNB)    // 524288 gather positions

typedef unsigned long long ull;

// ---- scratch (no allocation allowed; device globals; .bss zero-init) ----
__device__ int    g_cnt[NROWS];               // zeroed by k_pool for next replay
__device__ __half g_zt[NROWS * COUT];         // 8 MB z-tilde (pre-BN), fp16
__device__ float  g_part[256 * 512];          // rb*512 + cb*256 + q*128 + cc
__device__ __half g_sc_h[COUT];
__device__ __half g_sh_h[COUT];

// ---------------------------------------------------------------------------
__global__ void k_hist(const int* __restrict__ nbr) {
    int i = blockIdx.x * blockDim.x + threadIdx.x;
    if (i < NPOS) {
        int b = i >> 17;                    // / (V*NNB)
        atomicAdd(&g_cnt[(b << 12) + nbr[i]], 1);
    }
}

// ---------------------------------------------------------------------------
// z~ = [features | fdist] @ W^T + bias   (16384 x 128) @ (128 x 256)
// Block tile 64x128, K=128 resident. 256 threads, each 8 rows x 4 cols.
// Packed fma.rn.f32x2 mainloop. Emits weighted sum/sumsq partials.
__global__ void __launch_bounds__(256) k_gemm(const float* __restrict__ fm,
                                              const float* __restrict__ W,
                                              const float* __restrict__ bias) {
    extern __shared__ float sm[];
    float* As   = sm;                 // 64*128
    float* Ws   = sm + 64 * 128;      // 128*128 (float4-swizzled)
    float* cntf = Ws + 128 * 128;     // 64
    float* red  = As;                 // reused post-mainloop

    const int tid  = threadIdx.x;
    const int rb   = blockIdx.y;
    const int cb   = blockIdx.x;
    const int row0 = rb * 64;

    if (tid < 64) cntf[tid] = (float)g_cnt[row0 + tid];

    #pragma unroll
    for (int i = 0; i < 32; i++) {
        int e = i * 256 + tid;
        int r = e >> 7, k = e & 127;
        As[r * 128 + k] = (k < 127) ? fm[(row0 + r) * 127 + k] : 0.f;
    }

    // W transposed, float4-granular XOR swizzle: (k,c) -> Ws[k*128 + ((c>>2)^(k&31))*4 + (c&3)]
    #pragma unroll
    for (int i = 0; i < 16; i++) {
        int e  = i * 256 + tid;
        int c  = e >> 5;
        int k4 = e & 31;
        float4 wv = *reinterpret_cast<const float4*>(&W[(cb * 128 + c) * 128 + k4 * 4]);
        int cq = c >> 2, cl = c & 3;
        float wa[4] = {wv.x, wv.y, wv.z, wv.w};
        #pragma unroll
        for (int j = 0; j < 4; j++) {
            int k = k4 * 4 + j;
            Ws[k * 128 + ((cq ^ (k & 31)) << 2) + cl] = wa[j];
        }
    }
    __syncthreads();

    // fdist per row (deterministic shfl tree)
    {
        int w = tid >> 5, ln = tid & 31;
        #pragma unroll
        for (int rr = 0; rr < 8; rr++) {
            int r = w * 8 + rr;
            float s = 0.f;
            #pragma unroll
            for (int q = 0; q < 4; q++) {
                int k = q * 32 + ln;
                float a = (k < 127) ? As[r * 128 + k] : 0.f;
                s += a * a;
            }
            #pragma unroll
            for (int off = 16; off; off >>= 1)
                s += __shfl_xor_sync(0xffffffffu, s, off);
            if (ln == 0) As[r * 128 + 127] = sqrtf(s);
        }
    }
    __syncthreads();

    const int tc = tid & 31;
    const int tr = tid >> 5;
    ull acc2[8][2];
    #pragma unroll
    for (int m = 0; m < 8; m++) { acc2[m][0] = 0ull; acc2[m][1] = 0ull; }

    #pragma unroll 2
    for (int k0 = 0; k0 < 128; k0 += 4) {
        float4 av[8];
        #pragma unroll
        for (int m = 0; m < 8; m++)
            av[m] = *reinterpret_cast<const float4*>(&As[(tr * 8 + m) * 128 + k0]);
        #pragma unroll
        for (int j = 0; j < 4; j++) {
            int k = k0 + j;
            ulonglong2 w2 = *reinterpret_cast<const ulonglong2*>(
                &Ws[k * 128 + ((tc ^ (k & 31)) << 2)]);
            #pragma unroll
            for (int m = 0; m < 8; m++) {
                float a = (j == 0) ? av[m].x : (j == 1) ? av[m].y
                        : (j == 2) ? av[m].z : av[m].w;
                ull aa;
                asm("mov.b64 %0, {%1, %1};" : "=l"(aa) : "f"(a));
                asm("fma.rn.f32x2 %0, %1, %2, %0;" : "+l"(acc2[m][0]) : "l"(aa), "l"(w2.x));
                asm("fma.rn.f32x2 %0, %1, %2, %0;" : "+l"(acc2[m][1]) : "l"(aa), "l"(w2.y));
            }
        }
    }

    float4 bv = *reinterpret_cast<const float4*>(&bias[cb * 128 + tc * 4]);
    float ps[4] = {0.f, 0.f, 0.f, 0.f};
    float pq[4] = {0.f, 0.f, 0.f, 0.f};
    #pragma unroll
    for (int m = 0; m < 8; m++) {
        int gr   = row0 + tr * 8 + m;
        float cw = cntf[tr * 8 + m];
        float z0, z1, z2, z3;
        asm("mov.b64 {%0, %1}, %2;" : "=f"(z0), "=f"(z1) : "l"(acc2[m][0]));
        asm("mov.b64 {%0, %1}, %2;" : "=f"(z2), "=f"(z3) : "l"(acc2[m][1]));
        z0 += bv.x; z1 += bv.y; z2 += bv.z; z3 += bv.w;
        __half2 h01 = __floats2half2_rn(z0, z1);
        __half2 h23 = __floats2half2_rn(z2, z3);
        union { struct { __half2 a, b; } h; uint2 u; } pk;
        pk.h.a = h01; pk.h.b = h23;
        *reinterpret_cast<uint2*>(&g_zt[gr * COUT + cb * 128 + tc * 4]) = pk.u;
        ps[0] += cw * z0;  pq[0] += cw * z0 * z0;
        ps[1] += cw * z1;  pq[1] += cw * z1 * z1;
        ps[2] += cw * z2;  pq[2] += cw * z2 * z2;
        ps[3] += cw * z3;  pq[3] += cw * z3 * z3;
    }
    __syncthreads();
    #pragma unroll
    for (int j = 0; j < 4; j++) {
        red[tr * 128 + tc * 4 + j]        = ps[j];
        red[1024 + tr * 128 + tc * 4 + j] = pq[j];
    }
    __syncthreads();
    {
        int q = tid >> 7, c = tid & 127;
        float s = 0.f;
        #pragma unroll
        for (int t = 0; t < 8; t++) s += red[q * 1024 + t * 128 + c];
        g_part[rb * 512 + cb * 256 + q * 128 + c] = s;
    }
}

// ---------------------------------------------------------------------------
// One-block stats: 512 threads fold 256 row-block partials (4-way ILP, MLP),
// then emit per-channel BN scale/shift (fp16 for the pool).
__global__ void k_stats(const float* __restrict__ gamma,
                        const float* __restrict__ beta) {
    __shared__ float sred[512];
    int s = threadIdx.x;               // 0..511
    float a0 = 0.f, a1 = 0.f, a2 = 0.f, a3 = 0.f;
    #pragma unroll 16
    for (int rb = 0; rb < 256; rb += 4) {
        a0 += g_part[(rb + 0) * 512 + s];
        a1 += g_part[(rb + 1) * 512 + s];
        a2 += g_part[(rb + 2) * 512 + s];
        a3 += g_part[(rb + 3) * 512 + s];
    }
    sred[s] = (a0 + a1) + (a2 + a3);
    __syncthreads();
    if (s < 256) {
        int cb = s >> 7, cc = s & 127;
        float S = sred[cb * 256 + cc];
        float Q = sred[cb * 256 + 128 + cc];
        const float invN = 1.f / (float)NPOS;
        float mean = S * invN;
        float var  = Q * invN - mean * mean;
        float sc   = gamma[s] * rsqrtf(var + 1e-5f);
        float sh   = beta[s] - mean * sc;
        g_sc_h[s] = __float2half(sc);
        g_sh_h[s] = __float2half(sh);
    }
}

// ---------------------------------------------------------------------------
// Pool: 2 vertices per 256-thread block; thread = one channel-pair of one
// vertex. Theta chain in packed fp32 (fma.rn.f32x2), tail in half2.
__global__ void __launch_bounds__(256) k_pool(const int* __restrict__ nbr,
                                              const float* __restrict__ verts,
                                              const float* __restrict__ dirs,
                                              float* __restrict__ out) {
    __shared__ ull  sdw[2 * 32 * 3];   // duplicated {dw,dw} f32 pairs
    __shared__ int  soff[64];          // row offsets (in half2 units)
    const int bx  = blockIdx.x;        // vertex pair
    const int tid = threadIdx.x;

    if (tid < 64) {
        int v  = tid >> 5;             // which vertex of the pair
        int n  = tid & 31;
        int vb = bx * 2 + v;           // (b,v) linear
        int b  = vb >> 12;
        int j  = nbr[vb * 32 + n];
        float vx = verts[vb * 3 + 0];
        float vy = verts[vb * 3 + 1];
        float vz = verts[vb * 3 + 2];
        const float* pn = verts + ((b << 12) + j) * 3;
        float dx = pn[0] - vx, dy = pn[1] - vy, dz = pn[2] - vz;
        float nrm = fmaxf(sqrtf(dx * dx + dy * dy + dz * dz), 1e-12f);
        float inv = 1.f / nrm;
        float w0 = fmaf(dx * inv, 0.5f, 0.5f);
        float w1 = fmaf(dy * inv, 0.5f, 0.5f);
        float w2 = fmaf(dz * inv, 0.5f, 0.5f);
        ull p0, p1, p2;
        asm("mov.b64 %0, {%1, %1};" : "=l"(p0) : "f"(w0));
        asm("mov.b64 %0, {%1, %1};" : "=l"(p1) : "f"(w1));
        asm("mov.b64 %0, {%1, %1};" : "=l"(p2) : "f"(w2));
        sdw[(v * 32 + n) * 3 + 0] = p0;
        sdw[(v * 32 + n) * 3 + 1] = p1;
        sdw[(v * 32 + n) * 3 + 2] = p2;
        soff[v * 32 + n] = ((b << 12) + j) << 7;   // * 128 half2 per row
    }
    if (tid == 64) {                   // zero histogram slots for next replay
        g_cnt[bx * 2] = 0;
        g_cnt[bx * 2 + 1] = 0;
    }
    __syncthreads();

    const int v  = tid >> 7;           // vertex within pair
    const int cp = tid & 127;          // channel pair 0..127

    // channel-pair constants
    float d0a = dirs[2 * cp],       d0b = dirs[2 * cp + 1];
    float s0a = dirs[256 + 2 * cp] - d0a, s0b = dirs[256 + 2 * cp + 1] - d0b;
    float s1a = dirs[512 + 2 * cp] - d0a, s1b = dirs[512 + 2 * cp + 1] - d0b;
    float s2a = dirs[768 + 2 * cp] - d0a, s2b = dirs[768 + 2 * cp + 1] - d0b;
    ull d0p, s0p, s1p, s2p;
    asm("mov.b64 %0, {%1, %2};" : "=l"(d0p) : "f"(d0a), "f"(d0b));
    asm("mov.b64 %0, {%1, %2};" : "=l"(s0p) : "f"(s0a), "f"(s0b));
    asm("mov.b64 %0, {%1, %2};" : "=l"(s1p) : "f"(s1a), "f"(s1b));
    asm("mov.b64 %0, {%1, %2};" : "=l"(s2p) : "f"(s2a), "f"(s2b));

    __half2 sc2 = reinterpret_cast<const __half2*>(g_sc_h)[cp];
    __half2 sh2 = reinterpret_cast<const __half2*>(g_sh_h)[cp];
    const __half2 zero2 = __float2half2_rn(0.f);

    // gather all 32 neighbor half2 values (MLP = 32)
    const unsigned int* hzt = reinterpret_cast<const unsigned int*>(g_zt);
    unsigned int zv[32];
    #pragma unroll
    for (int n = 0; n < 32; n++)
        zv[n] = hzt[soff[v * 32 + n] + cp];

    __half2 acc2 = zero2;              // all candidates >= 0
    #pragma unroll
    for (int n = 0; n < 32; n++) {
        ull t = d0p;
        ull w0 = sdw[(v * 32 + n) * 3 + 0];
        ull w1 = sdw[(v * 32 + n) * 3 + 1];
        ull w2 = sdw[(v * 32 + n) * 3 + 2];
        asm("fma.rn.f32x2 %0, %1, %2, %0;" : "+l"(t) : "l"(w0), "l"(s0p));
        asm("fma.rn.f32x2 %0, %1, %2, %0;" : "+l"(t) : "l"(w1), "l"(s1p));
        asm("fma.rn.f32x2 %0, %1, %2, %0;" : "+l"(t) : "l"(w2), "l"(s2p));
        float t0, t1;
        asm("mov.b64 {%0, %1}, %2;" : "=f"(t0), "=f"(t1) : "l"(t));
        __half2 th2 = __hmax2(__floats2half2_rn(t0, t1), zero2);
        __half2 z2  = *reinterpret_cast<__half2*>(&zv[n]);
        __half2 r2  = __hmax2(__hfma2(z2, sc2, sh2), zero2);
        acc2 = __hmax2(acc2, __hmul2(r2, th2));
    }

    float2 o = __half22float2(acc2);
    *reinterpret_cast<float2*>(&out[(bx * 2 + v) * 256 + 2 * cp]) = o;
}

// ---------------------------------------------------------------------------
extern "C" void kernel_launch(void* const* d_in, const int* in_sizes, int n_in,
                              void* d_out, int out_size) {
    const int*   nbr   = (const int*)d_in[0];
    const float* verts = (const float*)d_in[1];
    const float* fm    = (const float*)d_in[2];
    const float* dirs  = (const float*)d_in[3];
    const float* W     = (const float*)d_in[4];
    const float* bias  = (const float*)d_in[5];
    const float* gamma = (const float*)d_in[6];
    const float* beta  = (const float*)d_in[7];
    float* out = (float*)d_out;

    const int smem_gemm = (64 * 128 + 128 * 128 + 64) * (int)sizeof(float); // 98,560 B
    cudaFuncSetAttribute(k_gemm, cudaFuncAttributeMaxDynamicSharedMemorySize, smem_gemm);

    k_hist<<<NPOS / 512, 512>>>(nbr);                    // launch 1
    k_gemm<<<dim3(2, 256), 256, smem_gemm>>>(fm, W, bias); // launch 2
    k_stats<<<1, 512>>>(gamma, beta);                    // launch 3
    k_pool<<<NROWS / 2, 256>>>(nbr, verts, dirs, out);   // launch 4 (profiled)
}